// round 1
// baseline (speedup 1.0000x reference)
#include <cuda_runtime.h>
#include <mma.h>
#include <cstdint>
#include <math.h>

using namespace nvcuda;

// Problem dims (SimpleLSTM): B=64, T=512, D=1024, H=1024
#define B_  64
#define T_  512
#define D_  1024
#define H_  1024
#define G4_ 4096   // 4*H

// ---------------- scratch (device globals: allocation-free) ----------------
__device__ float g_xproj[(size_t)T_ * B_ * G4_];   // [T][B][4H] fp32, 512 MB
__device__ float g_h[2][B_ * H_];                  // double-buffered hidden state
__device__ unsigned int g_bar_count = 0;
__device__ unsigned int g_bar_gen = 0;

// ---------------- software grid barrier (128 co-resident blocks) -----------
__device__ __forceinline__ void grid_sync_128() {
    __syncthreads();
    if (threadIdx.x == 0) {
        volatile unsigned int* genp = &g_bar_gen;
        unsigned int gen = *genp;
        __threadfence();                       // release: drain h writes to L2
        unsigned int old = atomicAdd(&g_bar_count, 1u);
        if (old == 127u) {
            atomicExch(&g_bar_count, 0u);
            __threadfence();
            atomicAdd(&g_bar_gen, 1u);
        } else {
            while (*genp == gen) { }
            __threadfence();                   // acquire
        }
    }
    __syncthreads();
}

// ============================================================================
// Kernel A: xproj[t][b][:] = xs[b][t][:] @ Wx        (M=T*B, N=4H, K=D), tf32
// Block tile 128x128x32, 8 warps (4x2), warp tile 32x64 (2x4 wmma frags)
// ============================================================================
__global__ void __launch_bounds__(256) xproj_kernel(const float* __restrict__ xs,
                                                    const float* __restrict__ Wx) {
    constexpr int BM = 128, BN = 128, BK = 32;
    constexpr int LDA = 36;    // padded, multiple of 4 (16B) -> aligned float4
    constexpr int LDB = 132;
    __shared__ float As[BM * LDA];
    __shared__ float Bs[BK * LDB];

    const int tid = threadIdx.x;
    const int m0 = blockIdx.y * BM;
    const int n0 = blockIdx.x * BN;
    const int w  = tid >> 5;
    const int wm = w & 3;      // 0..3 -> 32-row strip
    const int wn = w >> 2;     // 0..1 -> 64-col strip

    wmma::fragment<wmma::accumulator, 16, 16, 8, float> acc[2][4];
    #pragma unroll
    for (int i = 0; i < 2; i++)
        #pragma unroll
        for (int j = 0; j < 4; j++)
            wmma::fill_fragment(acc[i][j], 0.0f);

    for (int k0 = 0; k0 < D_; k0 += BK) {
        // A tile: rows are m = t*B + b  (time-major output ordering)
        #pragma unroll
        for (int it = 0; it < 4; it++) {
            int idx = tid + it * 256;          // 1024 float4 total
            int row = idx >> 3;
            int kq  = (idx & 7) * 4;
            int m   = m0 + row;
            int bb  = m & (B_ - 1);
            int tt  = m >> 6;
            float4 v = *reinterpret_cast<const float4*>(
                xs + ((size_t)bb * T_ + tt) * D_ + k0 + kq);
            *reinterpret_cast<float4*>(&As[row * LDA + kq]) = v;
        }
        // B tile: Wx[k][n]
        #pragma unroll
        for (int it = 0; it < 4; it++) {
            int idx = tid + it * 256;
            int row = idx >> 5;
            int cq  = (idx & 31) * 4;
            float4 v = *reinterpret_cast<const float4*>(
                Wx + (size_t)(k0 + row) * G4_ + n0 + cq);
            *reinterpret_cast<float4*>(&Bs[row * LDB + cq]) = v;
        }
        __syncthreads();

        #pragma unroll
        for (int kk = 0; kk < BK; kk += 8) {
            wmma::fragment<wmma::matrix_a, 16, 16, 8, wmma::precision::tf32, wmma::row_major> af[2];
            wmma::fragment<wmma::matrix_b, 16, 16, 8, wmma::precision::tf32, wmma::row_major> bf[4];
            #pragma unroll
            for (int mi = 0; mi < 2; mi++) {
                wmma::load_matrix_sync(af[mi], &As[(wm * 32 + mi * 16) * LDA + kk], LDA);
                #pragma unroll
                for (int i = 0; i < af[mi].num_elements; i++)
                    af[mi].x[i] = wmma::__float_to_tf32(af[mi].x[i]);
            }
            #pragma unroll
            for (int nj = 0; nj < 4; nj++) {
                wmma::load_matrix_sync(bf[nj], &Bs[kk * LDB + wn * 64 + nj * 16], LDB);
                #pragma unroll
                for (int i = 0; i < bf[nj].num_elements; i++)
                    bf[nj].x[i] = wmma::__float_to_tf32(bf[nj].x[i]);
            }
            #pragma unroll
            for (int mi = 0; mi < 2; mi++)
                #pragma unroll
                for (int nj = 0; nj < 4; nj++)
                    wmma::mma_sync(acc[mi][nj], af[mi], bf[nj], acc[mi][nj]);
        }
        __syncthreads();
    }

    #pragma unroll
    for (int mi = 0; mi < 2; mi++)
        #pragma unroll
        for (int nj = 0; nj < 4; nj++) {
            size_t row = (size_t)(m0 + wm * 32 + mi * 16);
            size_t col = (size_t)(n0 + wn * 64 + nj * 16);
            wmma::store_matrix_sync(g_xproj + row * G4_ + col, acc[mi][nj],
                                    G4_, wmma::mem_row_major);
        }
}

// ============================================================================
// Kernel B: persistent LSTM scan. 128 blocks:
//   block = (mh in {0,1}) x (jc in 0..63) -> rows [mh*32, +32), h-cols [jc*16, +16)
//   Per step: gates(own slice) = h @ Wh(4 gate col-groups) + xproj[t] + bias,
//   fused elementwise (c in registers), write new h slice + ys, grid barrier.
// 8 warps: warp = (mi in {0,1}) x (gate in 0..3), one 16x16 acc each.
// ============================================================================
__global__ void __launch_bounds__(256, 1) lstm_scan_kernel(
    const float* __restrict__ c0, const float* __restrict__ h0,
    const float* __restrict__ Wh, const float* __restrict__ bias,
    float* __restrict__ out)
{
    constexpr int LDS_ = 68;   // 64 + 4 pad, 16B-aligned rows
    __shared__ float hs[32 * LDS_];      // h rows (32 x 64 k-chunk)
    __shared__ float Whs[64 * LDS_];     // Wh   (64 k x 4 gates x 16 cols)
    __shared__ float sg[4][32][16];      // gate preacts (GEMM part)

    const int tid  = threadIdx.x;
    const int w    = tid >> 5;
    const int g    = w & 3;              // gate group
    const int mi   = w >> 2;             // row-frag within 32-row half
    const int mh   = blockIdx.x >> 6;
    const int jc   = blockIdx.x & 63;
    const int j0   = jc * 16;
    const int row0 = mh * 32;

    // per-thread ownership of 2 of the 512 (32x16) output elems
    int rr[2], cc[2];
    rr[0] = tid >> 4;          cc[0] = tid & 15;
    rr[1] = (tid + 256) >> 4;  cc[1] = (tid + 256) & 15;

    float creg[2];
    float bb[2][4];
    #pragma unroll
    for (int q = 0; q < 2; q++) {
        int bg = row0 + rr[q];
        int jg = j0 + cc[q];
        creg[q] = c0[(size_t)bg * H_ + jg];
        g_h[0][(size_t)bg * H_ + jg] = h0[(size_t)bg * H_ + jg];
        #pragma unroll
        for (int gg = 0; gg < 4; gg++) bb[q][gg] = bias[gg * H_ + jg];
    }
    grid_sync_128();

    for (int t = 0; t < T_; t++) {
        const float* hcur  = g_h[t & 1];
        float*       hnext = g_h[(t + 1) & 1];

        wmma::fragment<wmma::accumulator, 16, 16, 8, float> acc;
        wmma::fill_fragment(acc, 0.0f);

        for (int k0 = 0; k0 < H_; k0 += 64) {
            // stage h rows (L2-coherent reads; other SMs wrote them)
            #pragma unroll
            for (int it = 0; it < 2; it++) {
                int idx = tid + it * 256;          // 512 float4
                int r  = idx >> 4;
                int cq = (idx & 15) * 4;
                float4 v = __ldcg(reinterpret_cast<const float4*>(
                    hcur + (size_t)(row0 + r) * H_ + k0 + cq));
                *reinterpret_cast<float4*>(&hs[r * LDS_ + cq]) = v;
            }
            // stage Wh slice: 4 gate column groups of 16
            #pragma unroll
            for (int it = 0; it < 4; it++) {
                int idx = tid + it * 256;          // 1024 float4
                int r   = idx >> 4;
                int seg = (idx >> 2) & 3;
                int cq  = (idx & 3) * 4;
                float4 v = *reinterpret_cast<const float4*>(
                    Wh + (size_t)(k0 + r) * G4_ + seg * H_ + j0 + cq);
                *reinterpret_cast<float4*>(&Whs[r * LDS_ + seg * 16 + cq]) = v;
            }
            __syncthreads();
            #pragma unroll
            for (int kk = 0; kk < 64; kk += 8) {
                wmma::fragment<wmma::matrix_a, 16, 16, 8, wmma::precision::tf32, wmma::row_major> af;
                wmma::fragment<wmma::matrix_b, 16, 16, 8, wmma::precision::tf32, wmma::row_major> bf;
                wmma::load_matrix_sync(af, &hs[(mi * 16) * LDS_ + kk], LDS_);
                #pragma unroll
                for (int i = 0; i < af.num_elements; i++)
                    af.x[i] = wmma::__float_to_tf32(af.x[i]);
                wmma::load_matrix_sync(bf, &Whs[kk * LDS_ + g * 16], LDS_);
                #pragma unroll
                for (int i = 0; i < bf.num_elements; i++)
                    bf.x[i] = wmma::__float_to_tf32(bf.x[i]);
                wmma::mma_sync(acc, af, bf, acc);
            }
            __syncthreads();
        }
        wmma::store_matrix_sync(&sg[g][mi * 16][0], acc, 16, wmma::mem_row_major);
        __syncthreads();

        // fused elementwise: flax gate order i, f, g, o
        #pragma unroll
        for (int q = 0; q < 2; q++) {
            int r = rr[q], c = cc[q];
            int bg = row0 + r;
            int jg = j0 + c;
            const float* xp = g_xproj + ((size_t)t * B_ + bg) * G4_;
            float pi = sg[0][r][c] + xp[jg]           + bb[q][0];
            float pf = sg[1][r][c] + xp[H_ + jg]      + bb[q][1];
            float pg = sg[2][r][c] + xp[2 * H_ + jg]  + bb[q][2];
            float po = sg[3][r][c] + xp[3 * H_ + jg]  + bb[q][3];
            float si = 1.0f / (1.0f + expf(-pi));
            float sf = 1.0f / (1.0f + expf(-pf));
            float so = 1.0f / (1.0f + expf(-po));
            float tg = tanhf(pg);
            float cn = sf * creg[q] + si * tg;
            float hn = so * tanhf(cn);
            creg[q] = cn;
            hnext[(size_t)bg * H_ + jg] = hn;
            // ys[b][t][j] at offset 2*B*H
            out[2 * B_ * H_ + ((size_t)bg * T_ + t) * H_ + jg] = hn;
            if (t == T_ - 1)
                out[B_ * H_ + (size_t)bg * H_ + jg] = hn;   // hT
        }
        grid_sync_128();
    }

    // cT
    #pragma unroll
    for (int q = 0; q < 2; q++) {
        int bg = row0 + rr[q];
        int jg = j0 + cc[q];
        out[(size_t)bg * H_ + jg] = creg[q];
    }
}

// ============================================================================
// Launch: inputs in metadata order c0, h0, xs, Wx, Wh, b. Output fp32:
//   [cT (B*H)] [hT (B*H)] [ys (B*T*H)]
// ============================================================================
extern "C" void kernel_launch(void* const* d_in, const int* in_sizes, int n_in,
                              void* d_out, int out_size) {
    const float* c0   = (const float*)d_in[0];
    const float* h0   = (const float*)d_in[1];
    const float* xs   = (const float*)d_in[2];
    const float* Wx   = (const float*)d_in[3];
    const float* Wh   = (const float*)d_in[4];
    const float* bias = (const float*)d_in[5];
    float* out = (float*)d_out;

    dim3 gridA(G4_ / 128, (T_ * B_) / 128);   // 32 x 256 blocks
    xproj_kernel<<<gridA, 256>>>(xs, Wx);
    lstm_scan_kernel<<<128, 256>>>(c0, h0, Wh, bias, out);
}

// round 2
// speedup vs baseline: 1.2470x; 1.2470x over previous
#include <cuda_runtime.h>
#include <mma.h>
#include <cstdint>
#include <math.h>

using namespace nvcuda;

// Problem dims (SimpleLSTM): B=64, T=512, D=1024, H=1024
#define B_  64
#define T_  512
#define D_  1024
#define H_  1024
#define G4_ 4096   // 4*H

// ---------------- scratch (device globals: allocation-free) ----------------
__device__ float g_xproj[(size_t)T_ * B_ * G4_];   // [T][B][4H] fp32
__device__ float g_h[2][B_ * H_];                  // double-buffered hidden state
__device__ unsigned int g_bar_count = 0;
__device__ unsigned int g_bar_gen = 0;

// ---------------- cp.async helpers ----------------
__device__ __forceinline__ void cp_async16(void* dst, const void* src) {
    uint32_t s = (uint32_t)__cvta_generic_to_shared(dst);
    asm volatile("cp.async.cg.shared.global [%0], [%1], 16;\n" :: "r"(s), "l"(src));
}
__device__ __forceinline__ void cp_commit() { asm volatile("cp.async.commit_group;\n"); }
template<int N>
__device__ __forceinline__ void cp_wait() { asm volatile("cp.async.wait_group %0;\n" :: "n"(N)); }

// ---------------- software grid barrier (128 co-resident blocks) -----------
__device__ __forceinline__ void grid_sync_128() {
    __syncthreads();
    if (threadIdx.x == 0) {
        volatile unsigned int* genp = &g_bar_gen;
        unsigned int gen = *genp;
        __threadfence();                       // release: drain h writes to L2
        unsigned int old = atomicAdd(&g_bar_count, 1u);
        if (old == 127u) {
            atomicExch(&g_bar_count, 0u);
            __threadfence();
            atomicAdd(&g_bar_gen, 1u);
        } else {
            while (*genp == gen) { }
            __threadfence();                   // acquire
        }
    }
    __syncthreads();
}

// ============================================================================
// Kernel A: xproj[t][b][:] = xs[b][t][:] @ Wx   (M=T*B=32768, N=4096, K=1024)
// tf32 wmma, 128x128x32 tile, cp.async double-buffered pipeline.
// ============================================================================
__global__ void __launch_bounds__(256) xproj_kernel(const float* __restrict__ xs,
                                                    const float* __restrict__ Wx) {
    constexpr int LDA = 36;   // 32 + 4 pad (16B multiple)
    constexpr int LDB = 132;  // 128 + 4 pad
    extern __shared__ float sm[];
    float* As = sm;                       // [2][128*LDA]
    float* Bs = sm + 2 * 128 * LDA;       // [2][32*LDB]

    const int tid = threadIdx.x;
    const int m0 = blockIdx.y * 128;
    const int n0 = blockIdx.x * 128;
    const int w  = tid >> 5;
    const int wm = w & 3;      // 4 strips of 32 rows
    const int wn = w >> 2;     // 2 strips of 64 cols

    wmma::fragment<wmma::accumulator, 16, 16, 8, float> acc[2][4];
    #pragma unroll
    for (int i = 0; i < 2; i++)
        #pragma unroll
        for (int j = 0; j < 4; j++)
            wmma::fill_fragment(acc[i][j], 0.0f);

    auto load_stage = [&](int st, int k0) {
        #pragma unroll
        for (int it = 0; it < 4; it++) {
            int idx = tid + it * 256;              // 1024 float4
            int row = idx >> 3;
            int q   = (idx & 7) * 4;
            int m   = m0 + row;
            int bb  = m & (B_ - 1);
            int tt  = m >> 6;
            cp_async16(&As[st * 128 * LDA + row * LDA + q],
                       xs + ((size_t)bb * T_ + tt) * D_ + k0 + q);
        }
        #pragma unroll
        for (int it = 0; it < 4; it++) {
            int idx = tid + it * 256;              // 1024 float4
            int row = idx >> 5;
            int q   = (idx & 31) * 4;
            cp_async16(&Bs[st * 32 * LDB + row * LDB + q],
                       Wx + (size_t)(k0 + row) * G4_ + n0 + q);
        }
    };

    load_stage(0, 0);
    cp_commit();

    for (int kc = 0; kc < 32; kc++) {
        if (kc + 1 < 32) load_stage((kc + 1) & 1, (kc + 1) * 32);
        cp_commit();
        cp_wait<1>();
        __syncthreads();

        const float* a_base = &As[(kc & 1) * 128 * LDA];
        const float* b_base = &Bs[(kc & 1) * 32 * LDB];
        #pragma unroll
        for (int kk = 0; kk < 32; kk += 8) {
            wmma::fragment<wmma::matrix_a, 16, 16, 8, wmma::precision::tf32, wmma::row_major> af[2];
            wmma::fragment<wmma::matrix_b, 16, 16, 8, wmma::precision::tf32, wmma::row_major> bf[4];
            #pragma unroll
            for (int mi = 0; mi < 2; mi++) {
                wmma::load_matrix_sync(af[mi], a_base + (wm * 32 + mi * 16) * LDA + kk, LDA);
                #pragma unroll
                for (int i = 0; i < af[mi].num_elements; i++)
                    af[mi].x[i] = wmma::__float_to_tf32(af[mi].x[i]);
            }
            #pragma unroll
            for (int nj = 0; nj < 4; nj++) {
                wmma::load_matrix_sync(bf[nj], b_base + kk * LDB + wn * 64 + nj * 16, LDB);
                #pragma unroll
                for (int i = 0; i < bf[nj].num_elements; i++)
                    bf[nj].x[i] = wmma::__float_to_tf32(bf[nj].x[i]);
            }
            #pragma unroll
            for (int mi = 0; mi < 2; mi++)
                #pragma unroll
                for (int nj = 0; nj < 4; nj++)
                    wmma::mma_sync(acc[mi][nj], af[mi], bf[nj], acc[mi][nj]);
        }
        __syncthreads();
    }

    #pragma unroll
    for (int mi = 0; mi < 2; mi++)
        #pragma unroll
        for (int nj = 0; nj < 4; nj++) {
            size_t row = (size_t)(m0 + wm * 32 + mi * 16);
            size_t col = (size_t)(n0 + wn * 64 + nj * 16);
            wmma::store_matrix_sync(g_xproj + row * G4_ + col, acc[mi][nj],
                                    G4_, wmma::mem_row_major);
        }
}

// ============================================================================
// Kernel B: persistent LSTM scan, 128 blocks.
//   Block jb owns h-cols [jb*8, jb*8+8) for the FULL batch (M=64).
//   Its Wh slice (1024 x 4gates x 8cols = 32 gate-cols) lives in SMEM for the
//   whole kernel. Per step: read full h (64x1024) via cp.async.cg double
//   buffering, tf32 wmma (64x32x1024), fused elementwise, grid barrier.
//   8 warps: wm = w&3 (16-row strip), wn = w>>2 (16-gatecol strip); 1 acc each.
// ============================================================================
__global__ void __launch_bounds__(256, 1) lstm_scan_kernel(
    const float* __restrict__ c0, const float* __restrict__ h0,
    const float* __restrict__ Wh, const float* __restrict__ bias,
    float* __restrict__ out)
{
    constexpr int LDW = 36;    // Wh slice row: 32 cols + 4 pad
    constexpr int LDH = 132;   // h chunk row: 128 k + 4 pad
    constexpr int LDS = 36;    // gate staging row: 32 + 4 pad
    extern __shared__ float sm[];
    float* Whs = sm;                          // [1024*36]
    float* hs  = Whs + 1024 * LDW;            // [2][64*132]
    float* sg  = hs + 2 * 64 * LDH;           // [64*36]

    const int tid = threadIdx.x;
    const int w   = tid >> 5;
    const int wm  = w & 3;                    // m strip (16 rows of 64)
    const int wn  = w >> 2;                   // n strip (16 of 32 gate cols)
    const int j0  = blockIdx.x * 8;           // owned h-columns

    // ---- load Wh slice into SMEM (once): col n = gate(n>>3)*H + j0 + (n&7)
    for (int i = tid; i < 8192; i += 256) {   // 8192 float4
        int k   = i >> 3;
        int rem = i & 7;
        int g   = rem >> 1;
        int q   = (rem & 1) * 4;
        *reinterpret_cast<float4*>(&Whs[k * LDW + g * 8 + q]) =
            *reinterpret_cast<const float4*>(Wh + (size_t)k * G4_ + g * H_ + j0 + q);
    }

    // ---- per-thread ownership of 2 of the 512 (64 x 8) outputs
    int eb[2], ej[2];
    float creg[2], bb4[2][4];
    #pragma unroll
    for (int qq = 0; qq < 2; qq++) {
        int e = tid + qq * 256;
        eb[qq] = e >> 3;
        ej[qq] = e & 7;
        int b = eb[qq], j = j0 + ej[qq];
        creg[qq] = c0[(size_t)b * H_ + j];
        g_h[0][(size_t)b * H_ + j] = h0[(size_t)b * H_ + j];
        #pragma unroll
        for (int g = 0; g < 4; g++) bb4[qq][g] = bias[g * H_ + j];
    }
    grid_sync_128();   // Whs + h0 visible everywhere

    for (int t = 0; t < T_; t++) {
        const float* hcur  = g_h[t & 1];
        float*       hnext = g_h[(t + 1) & 1];

        // prefetch this step's xproj values early (DRAM latency hidden by GEMM)
        float xpr[2][4];
        {
            const float* xp = g_xproj + ((size_t)t * B_) * G4_;
            #pragma unroll
            for (int qq = 0; qq < 2; qq++) {
                const float* xpb = xp + (size_t)eb[qq] * G4_ + j0 + ej[qq];
                #pragma unroll
                for (int g = 0; g < 4; g++) xpr[qq][g] = __ldg(xpb + g * H_);
            }
        }

        wmma::fragment<wmma::accumulator, 16, 16, 8, float> acc;
        wmma::fill_fragment(acc, 0.0f);

        auto load_h = [&](int st, int k0) {
            #pragma unroll
            for (int it = 0; it < 8; it++) {
                int idx = tid + it * 256;          // 2048 float4 (64 rows x 128 k)
                int r   = idx >> 5;
                int cq  = (idx & 31) * 4;
                cp_async16(&hs[st * 64 * LDH + r * LDH + cq],
                           hcur + (size_t)r * H_ + k0 + cq);
            }
        };

        load_h(0, 0);
        cp_commit();
        for (int c = 0; c < 8; c++) {              // 8 chunks of 128 k
            if (c + 1 < 8) load_h((c + 1) & 1, (c + 1) * 128);
            cp_commit();
            cp_wait<1>();
            __syncthreads();

            const float* hb = &hs[(c & 1) * 64 * LDH + (wm * 16) * LDH];
            #pragma unroll
            for (int kk = 0; kk < 128; kk += 8) {
                wmma::fragment<wmma::matrix_a, 16, 16, 8, wmma::precision::tf32, wmma::row_major> af;
                wmma::fragment<wmma::matrix_b, 16, 16, 8, wmma::precision::tf32, wmma::row_major> bf;
                wmma::load_matrix_sync(af, hb + kk, LDH);
                #pragma unroll
                for (int i = 0; i < af.num_elements; i++)
                    af.x[i] = wmma::__float_to_tf32(af.x[i]);
                wmma::load_matrix_sync(bf, &Whs[(c * 128 + kk) * LDW + wn * 16], LDW);
                #pragma unroll
                for (int i = 0; i < bf.num_elements; i++)
                    bf.x[i] = wmma::__float_to_tf32(bf.x[i]);
                wmma::mma_sync(acc, af, bf, acc);
            }
            __syncthreads();
        }

        wmma::store_matrix_sync(&sg[(wm * 16) * LDS + wn * 16], acc, LDS,
                                wmma::mem_row_major);
        __syncthreads();

        // fused elementwise, flax gate order i, f, g, o
        #pragma unroll
        for (int qq = 0; qq < 2; qq++) {
            int b = eb[qq], jj = ej[qq];
            int j = j0 + jj;
            float pi = sg[b * LDS + jj]       + xpr[qq][0] + bb4[qq][0];
            float pf = sg[b * LDS + 8 + jj]   + xpr[qq][1] + bb4[qq][1];
            float pg = sg[b * LDS + 16 + jj]  + xpr[qq][2] + bb4[qq][2];
            float po = sg[b * LDS + 24 + jj]  + xpr[qq][3] + bb4[qq][3];
            float si = 1.0f / (1.0f + expf(-pi));
            float sf = 1.0f / (1.0f + expf(-pf));
            float so = 1.0f / (1.0f + expf(-po));
            float tg = tanhf(pg);
            float cn = sf * creg[qq] + si * tg;
            float hn = so * tanhf(cn);
            creg[qq] = cn;
            hnext[(size_t)b * H_ + j] = hn;
            out[2 * B_ * H_ + ((size_t)b * T_ + t) * H_ + j] = hn;   // ys
            if (t == T_ - 1)
                out[B_ * H_ + (size_t)b * H_ + j] = hn;              // hT
        }
        grid_sync_128();
    }

    // cT
    #pragma unroll
    for (int qq = 0; qq < 2; qq++) {
        int b = eb[qq], j = j0 + ej[qq];
        out[(size_t)b * H_ + j] = creg[qq];
    }
}

// ============================================================================
// Launch. Inputs: c0, h0, xs, Wx, Wh, b. Output fp32: [cT][hT][ys]
// ============================================================================
extern "C" void kernel_launch(void* const* d_in, const int* in_sizes, int n_in,
                              void* d_out, int out_size) {
    const float* c0   = (const float*)d_in[0];
    const float* h0   = (const float*)d_in[1];
    const float* xs   = (const float*)d_in[2];
    const float* Wx   = (const float*)d_in[3];
    const float* Wh   = (const float*)d_in[4];
    const float* bias = (const float*)d_in[5];
    float* out = (float*)d_out;

    constexpr int XPROJ_SMEM = (2 * 128 * 36 + 2 * 32 * 132) * 4;            // 70,656 B
    constexpr int SCAN_SMEM  = (1024 * 36 + 2 * 64 * 132 + 64 * 36) * 4;     // 224,256 B
    cudaFuncSetAttribute(xproj_kernel,
                         cudaFuncAttributeMaxDynamicSharedMemorySize, XPROJ_SMEM);
    cudaFuncSetAttribute(lstm_scan_kernel,
                         cudaFuncAttributeMaxDynamicSharedMemorySize, SCAN_SMEM);

    dim3 gridA(G4_ / 128, (T_ * B_) / 128);   // 32 x 256 blocks
    xproj_kernel<<<gridA, 256, XPROJ_SMEM>>>(xs, Wx);
    lstm_scan_kernel<<<128, 256, SCAN_SMEM>>>(c0, h0, Wh, bias, out);
}

// round 3
// speedup vs baseline: 2.0687x; 1.6589x over previous
#include <cuda_runtime.h>
#include <mma.h>
#include <cstdint>
#include <math.h>

using namespace nvcuda;

// Problem dims (SimpleLSTM): B=64, T=512, D=1024, H=1024
#define B_  64
#define T_  512
#define D_  1024
#define H_  1024
#define G4_ 4096   // 4*H

// ---------------- scratch (device globals: allocation-free) ----------------
__device__ float g_xproj[(size_t)T_ * B_ * G4_];   // [T][B][4H] fp32
// hidden state in PERMUTED mma-A-fragment layout, double buffered:
//   [strip(4)][ki(128)][lane(32)][v(4)]
//   v0 = h[strip*16 + lane/4     ][8ki + lane%4    ]
//   v1 = h[strip*16 + lane/4 + 8 ][8ki + lane%4    ]
//   v2 = h[strip*16 + lane/4     ][8ki + lane%4 + 4]
//   v3 = h[strip*16 + lane/4 + 8 ][8ki + lane%4 + 4]
__device__ float g_hperm[2][B_ * H_];
__device__ unsigned int g_bar_count = 0;
__device__ unsigned int g_bar_gen = 0;

// ---------------- helpers ----------------
__device__ __forceinline__ void cp_async16(void* dst, const void* src) {
    uint32_t s = (uint32_t)__cvta_generic_to_shared(dst);
    asm volatile("cp.async.cg.shared.global [%0], [%1], 16;\n" :: "r"(s), "l"(src));
}
__device__ __forceinline__ void cp_commit() { asm volatile("cp.async.commit_group;\n"); }
template<int N>
__device__ __forceinline__ void cp_wait() { asm volatile("cp.async.wait_group %0;\n" :: "n"(N)); }

__device__ __forceinline__ float tf32_rnaf(float x) {
    unsigned r;
    asm("cvt.rna.tf32.f32 %0, %1;" : "=r"(r) : "f"(x));
    return __uint_as_float(r);
}

__device__ __forceinline__ void mma_tf32(float4& d, const uint4& a,
                                         unsigned b0, unsigned b1) {
    asm volatile(
        "mma.sync.aligned.m16n8k8.row.col.f32.tf32.tf32.f32 "
        "{%0,%1,%2,%3}, {%4,%5,%6,%7}, {%8,%9}, {%0,%1,%2,%3};"
        : "+f"(d.x), "+f"(d.y), "+f"(d.z), "+f"(d.w)
        : "r"(a.x), "r"(a.y), "r"(a.z), "r"(a.w), "r"(b0), "r"(b1));
}

__device__ __forceinline__ float sigmoid_f(float x) {
    return __fdividef(1.0f, 1.0f + __expf(-x));
}
__device__ __forceinline__ float tanh_f(float x) {
    return __fdividef(2.0f, 1.0f + __expf(-2.0f * x)) - 1.0f;
}

// ============================================================================
// Kernel A: xproj = xs @ Wx  (M=32768, N=4096, K=1024), tf32 wmma, cp.async
// (unchanged from round 2 — ~1.6ms, not the bottleneck)
// ============================================================================
__global__ void __launch_bounds__(256) xproj_kernel(const float* __restrict__ xs,
                                                    const float* __restrict__ Wx) {
    constexpr int LDA = 36;
    constexpr int LDB = 132;
    extern __shared__ float sm[];
    float* As = sm;
    float* Bs = sm + 2 * 128 * LDA;

    const int tid = threadIdx.x;
    const int m0 = blockIdx.y * 128;
    const int n0 = blockIdx.x * 128;
    const int w  = tid >> 5;
    const int wm = w & 3;
    const int wn = w >> 2;

    wmma::fragment<wmma::accumulator, 16, 16, 8, float> acc[2][4];
    #pragma unroll
    for (int i = 0; i < 2; i++)
        #pragma unroll
        for (int j = 0; j < 4; j++)
            wmma::fill_fragment(acc[i][j], 0.0f);

    auto load_stage = [&](int st, int k0) {
        #pragma unroll
        for (int it = 0; it < 4; it++) {
            int idx = tid + it * 256;
            int row = idx >> 3;
            int q   = (idx & 7) * 4;
            int m   = m0 + row;
            int bb  = m & (B_ - 1);
            int tt  = m >> 6;
            cp_async16(&As[st * 128 * LDA + row * LDA + q],
                       xs + ((size_t)bb * T_ + tt) * D_ + k0 + q);
        }
        #pragma unroll
        for (int it = 0; it < 4; it++) {
            int idx = tid + it * 256;
            int row = idx >> 5;
            int q   = (idx & 31) * 4;
            cp_async16(&Bs[st * 32 * LDB + row * LDB + q],
                       Wx + (size_t)(k0 + row) * G4_ + n0 + q);
        }
    };

    load_stage(0, 0);
    cp_commit();

    for (int kc = 0; kc < 32; kc++) {
        if (kc + 1 < 32) load_stage((kc + 1) & 1, (kc + 1) * 32);
        cp_commit();
        cp_wait<1>();
        __syncthreads();

        const float* a_base = &As[(kc & 1) * 128 * LDA];
        const float* b_base = &Bs[(kc & 1) * 32 * LDB];
        #pragma unroll
        for (int kk = 0; kk < 32; kk += 8) {
            wmma::fragment<wmma::matrix_a, 16, 16, 8, wmma::precision::tf32, wmma::row_major> af[2];
            wmma::fragment<wmma::matrix_b, 16, 16, 8, wmma::precision::tf32, wmma::row_major> bf[4];
            #pragma unroll
            for (int mi = 0; mi < 2; mi++) {
                wmma::load_matrix_sync(af[mi], a_base + (wm * 32 + mi * 16) * LDA + kk, LDA);
                #pragma unroll
                for (int i = 0; i < af[mi].num_elements; i++)
                    af[mi].x[i] = wmma::__float_to_tf32(af[mi].x[i]);
            }
            #pragma unroll
            for (int nj = 0; nj < 4; nj++) {
                wmma::load_matrix_sync(bf[nj], b_base + kk * LDB + wn * 64 + nj * 16, LDB);
                #pragma unroll
                for (int i = 0; i < bf[nj].num_elements; i++)
                    bf[nj].x[i] = wmma::__float_to_tf32(bf[nj].x[i]);
            }
            #pragma unroll
            for (int mi = 0; mi < 2; mi++)
                #pragma unroll
                for (int nj = 0; nj < 4; nj++)
                    wmma::mma_sync(acc[mi][nj], af[mi], bf[nj], acc[mi][nj]);
        }
        __syncthreads();
    }

    #pragma unroll
    for (int mi = 0; mi < 2; mi++)
        #pragma unroll
        for (int nj = 0; nj < 4; nj++) {
            size_t row = (size_t)(m0 + wm * 32 + mi * 16);
            size_t col = (size_t)(n0 + wn * 64 + nj * 16);
            wmma::store_matrix_sync(g_xproj + row * G4_ + col, acc[mi][nj],
                                    G4_, wmma::mem_row_major);
        }
}

// ============================================================================
// Kernel B: persistent LSTM scan, 128 blocks x 128 threads (4 warps).
//   Block owns h-cols [bIdx*8, +8) x full batch; Wh slice (1024x32 gate-cols)
//   lives tf32-rounded + fragment-permuted + gate-interleaved in SMEM.
//   Warps: wm = w&1 (32-row strip), wn = w>>1 (4 j-cols x 4 gates = 16 cols).
//   Per ki: 2 LDS.128 (a) + 1 LDS.128 (b, both n-frags) + 4 HMMA. No converts.
//   Epilogue entirely in registers (gate interleave puts i,f,g,o of a cell in
//   one thread's accs). h written tf32-rounded to g_hperm; ys full precision.
// ============================================================================
__global__ void __launch_bounds__(128, 1) lstm_scan_kernel(
    const float* __restrict__ c0, const float* __restrict__ h0,
    const float* __restrict__ Wh, const float* __restrict__ bias,
    float* __restrict__ out)
{
    extern __shared__ float sm[];
    float* Whs = sm;              // [wn(2)][ki(128)][lane(32)][v(4)] = 32768 floats
    float* hs  = sm + 32768;      // [stage(3)][strip(4)][ki2(16)][lane(32)][v(4)] = 24576

    const int tid  = threadIdx.x;
    const int w    = tid >> 5;
    const int lane = tid & 31;
    const int wm   = w & 1;       // 32-row strip (strips 2wm, 2wm+1)
    const int wn   = w >> 1;      // 16-col strip
    const int bIdx = blockIdx.x;
    const int j0   = bIdx * 8;
    const int q    = lane & 3;
    const int r0   = lane >> 2;   // 0..7
    const int j    = j0 + wn * 4 + q;   // this thread's h column

    // ---- build Whs: tf32-rounded, fragment-permuted, gate-interleaved.
    // warp-col c in [0,16): q(c) = (c&7)>>1, gate(c) = ((c>>3)<<1)|(c&1)
    for (int i = tid; i < 32768; i += 128) {
        int v   = i & 3;
        int ln  = (i >> 2) & 31;
        int ki  = (i >> 7) & 127;
        int wns = i >> 14;
        int k   = 8 * ki + (ln & 3) + ((v & 1) << 2);
        int c   = (ln >> 2) + ((v >> 1) << 3);
        int qq  = (c & 7) >> 1;
        int gate = ((c >> 3) << 1) | (c & 1);
        float val = Wh[(size_t)k * G4_ + gate * H_ + j0 + wns * 4 + qq];
        sm[i] = tf32_rnaf(val);
    }

    // ---- thread's 4 cells: rows wm*32 + r0 + {0,8,16,24}, column j
    int br[4];
    #pragma unroll
    for (int i = 0; i < 4; i++) br[i] = wm * 32 + r0 + i * 8;

    float creg[4], bia[4];
    #pragma unroll
    for (int g = 0; g < 4; g++) bia[g] = bias[g * H_ + j];
    #pragma unroll
    for (int i = 0; i < 4; i++) creg[i] = c0[(size_t)br[i] * H_ + j];

    // ---- init g_hperm[0] (tf32-rounded h0), this block covers ki = bIdx
    #pragma unroll
    for (int p = 0; p < 2; p++) {
        int s = wm * 2 + p;
        float2 v = make_float2(tf32_rnaf(h0[(size_t)br[2 * p] * H_ + j]),
                               tf32_rnaf(h0[(size_t)br[2 * p + 1] * H_ + j]));
        *reinterpret_cast<float2*>(
            &g_hperm[0][(((size_t)s * 128 + bIdx) * 32 + lane) * 4 + 2 * wn]) = v;
    }

    // ---- xproj prefetch
    float xpr[4][4];
    auto prefetch_xp = [&](int t) {
        const float* xp = g_xproj + (size_t)t * B_ * G4_;
        #pragma unroll
        for (int i = 0; i < 4; i++)
            #pragma unroll
            for (int g = 0; g < 4; g++)
                xpr[i][g] = __ldg(xp + (size_t)br[i] * G4_ + g * H_ + j);
    };
    prefetch_xp(0);

    // ---- initial full grid sync (Whs local; g_hperm[0] global)
    __syncthreads();
    if (tid == 0) {
        volatile unsigned int* genp = &g_bar_gen;
        unsigned int gen = *genp;
        __threadfence();
        unsigned int old = atomicAdd(&g_bar_count, 1u);
        if (old == 127u) {
            atomicExch(&g_bar_count, 0u);
            __threadfence();
            atomicAdd(&g_bar_gen, 1u);
        } else {
            while (*genp == gen) { }
            __threadfence();
        }
    }
    __syncthreads();

    for (int t = 0; t < T_; t++) {
        const float* hcur  = g_hperm[t & 1];
        float*       hnext = g_hperm[(t + 1) & 1];

        // chunk ch = ki range [16ch, 16ch+16) for all 4 strips (4 x 8KB runs)
        auto issue = [&](int ch) {
            float* dst = hs + (ch % 3) * 8192;
            #pragma unroll
            for (int it = 0; it < 16; it++) {
                int idx   = (tid + it * 128) * 4;      // float index in stage
                int strip = idx >> 11;
                int rem   = idx & 2047;
                cp_async16(dst + idx, hcur + strip * 16384 + ch * 2048 + rem);
            }
        };

        issue(0); cp_commit();
        issue(1); cp_commit();

        float4 acc[2][2];   // [mi][ni]
        #pragma unroll
        for (int a = 0; a < 2; a++)
            #pragma unroll
            for (int b = 0; b < 2; b++)
                acc[a][b] = make_float4(0.f, 0.f, 0.f, 0.f);

        #pragma unroll 1
        for (int ch = 0; ch < 8; ch++) {
            if (ch < 6) cp_wait<1>(); else cp_wait<0>();
            __syncthreads();
            if (ch + 2 < 8) { issue(ch + 2); cp_commit(); }

            const float* st = hs + (ch % 3) * 8192;
            const float* sa0 = st + (2 * wm) * 2048 + lane * 4;
            const float* sa1 = st + (2 * wm + 1) * 2048 + lane * 4;
            const float* sb  = Whs + wn * 16384 + ch * 2048 + lane * 4;
            #pragma unroll
            for (int ki2 = 0; ki2 < 16; ki2++) {
                uint4 a0 = *reinterpret_cast<const uint4*>(sa0 + ki2 * 128);
                uint4 a1 = *reinterpret_cast<const uint4*>(sa1 + ki2 * 128);
                uint4 b  = *reinterpret_cast<const uint4*>(sb + ki2 * 128);
                mma_tf32(acc[0][0], a0, b.x, b.y);
                mma_tf32(acc[0][1], a0, b.z, b.w);
                mma_tf32(acc[1][0], a1, b.x, b.y);
                mma_tf32(acc[1][1], a1, b.z, b.w);
            }
        }

        // ---- epilogue in registers (cell = mi*2 + upper)
        float hnv[4];
        #pragma unroll
        for (int cell = 0; cell < 4; cell++) {
            int mi = cell >> 1;
            int up = cell & 1;
            float gi = up ? acc[mi][0].z : acc[mi][0].x;
            float gf = up ? acc[mi][0].w : acc[mi][0].y;
            float gg = up ? acc[mi][1].z : acc[mi][1].x;
            float go = up ? acc[mi][1].w : acc[mi][1].y;
            float pi = gi + xpr[cell][0] + bia[0];
            float pf = gf + xpr[cell][1] + bia[1];
            float pg = gg + xpr[cell][2] + bia[2];
            float po = go + xpr[cell][3] + bia[3];
            float cn = sigmoid_f(pf) * creg[cell] + sigmoid_f(pi) * tanh_f(pg);
            float hn = sigmoid_f(po) * tanh_f(cn);
            creg[cell] = cn;
            hnv[cell] = hn;
        }

        // ---- write hnext (tf32-rounded, permuted)
        #pragma unroll
        for (int p = 0; p < 2; p++) {
            int s = wm * 2 + p;
            float2 v = make_float2(tf32_rnaf(hnv[2 * p]), tf32_rnaf(hnv[2 * p + 1]));
            *reinterpret_cast<float2*>(
                &hnext[(((size_t)s * 128 + bIdx) * 32 + lane) * 4 + 2 * wn]) = v;
        }

        // ---- barrier arrive
        __syncthreads();
        unsigned int mygen = 0;
        if (tid == 0) {
            volatile unsigned int* genp = &g_bar_gen;
            mygen = *genp;
            __threadfence();                    // release h stores
            unsigned int old = atomicAdd(&g_bar_count, 1u);
            if (old == 127u) {
                atomicExch(&g_bar_count, 0u);
                __threadfence();
                atomicAdd(&g_bar_gen, 1u);
            }
        }

        // ---- hidden work between arrive and wait: ys stores + next prefetch
        #pragma unroll
        for (int cell = 0; cell < 4; cell++)
            out[2 * B_ * H_ + ((size_t)br[cell] * T_ + t) * H_ + j] = hnv[cell];
        if (t == T_ - 1) {
            #pragma unroll
            for (int cell = 0; cell < 4; cell++)
                out[B_ * H_ + (size_t)br[cell] * H_ + j] = hnv[cell];
        }
        if (t + 1 < T_) prefetch_xp(t + 1);

        // ---- barrier wait
        if (tid == 0) {
            volatile unsigned int* genp = &g_bar_gen;
            while (*genp == mygen) { }
            __threadfence();                    // acquire
        }
        __syncthreads();
    }

    // cT (full precision chain)
    #pragma unroll
    for (int cell = 0; cell < 4; cell++)
        out[(size_t)br[cell] * H_ + j] = creg[cell];
}

// ============================================================================
// Launch. Inputs: c0, h0, xs, Wx, Wh, b. Output fp32: [cT][hT][ys]
// ============================================================================
extern "C" void kernel_launch(void* const* d_in, const int* in_sizes, int n_in,
                              void* d_out, int out_size) {
    const float* c0   = (const float*)d_in[0];
    const float* h0   = (const float*)d_in[1];
    const float* xs   = (const float*)d_in[2];
    const float* Wx   = (const float*)d_in[3];
    const float* Wh   = (const float*)d_in[4];
    const float* bias = (const float*)d_in[5];
    float* out = (float*)d_out;

    constexpr int XPROJ_SMEM = (2 * 128 * 36 + 2 * 32 * 132) * 4;   // 70,656 B
    constexpr int SCAN_SMEM  = (32768 + 3 * 8192) * 4;              // 229,376 B
    cudaFuncSetAttribute(xproj_kernel,
                         cudaFuncAttributeMaxDynamicSharedMemorySize, XPROJ_SMEM);
    cudaFuncSetAttribute(lstm_scan_kernel,
                         cudaFuncAttributeMaxDynamicSharedMemorySize, SCAN_SMEM);

    dim3 gridA(G4_ / 128, (T_ * B_) / 128);   // 32 x 256 blocks
    xproj_kernel<<<gridA, 256, XPROJ_SMEM>>>(xs, Wx);
    lstm_scan_kernel<<<128, 128, SCAN_SMEM>>>(c0, h0, Wh, bias, out);
}

// round 5
// speedup vs baseline: 2.1121x; 1.0210x over previous
#include <cuda_runtime.h>
#include <mma.h>
#include <cstdint>
#include <math.h>

using namespace nvcuda;

// Problem dims (SimpleLSTM): B=64, T=512, D=1024, H=1024
#define B_  64
#define T_  512
#define D_  1024
#define H_  1024
#define G4_ 4096   // 4*H

// ---------------- scratch (device globals: allocation-free) ----------------
__device__ float g_xproj[(size_t)T_ * B_ * G4_];   // [T*B][4H] fp32 (m = t*64+b)
// hidden state, A-frag permuted, f4 layout [ki(128)][strip(4)][lane(32)], v(4):
//   v0=h[strip*16 + ln/4][8ki + ln%4], v1=row+8, v2=col+4, v3=row+8,col+4
__device__ float g_hperm[2][B_ * H_];
__device__ unsigned int g_bar_count = 0;
__device__ unsigned int g_bar_gen = 0;

// ---------------- helpers ----------------
__device__ __forceinline__ void cp_async16(void* dst, const void* src) {
    uint32_t s = (uint32_t)__cvta_generic_to_shared(dst);
    asm volatile("cp.async.cg.shared.global [%0], [%1], 16;\n" :: "r"(s), "l"(src));
}
__device__ __forceinline__ void cp_commit() { asm volatile("cp.async.commit_group;\n"); }
template<int N>
__device__ __forceinline__ void cp_wait() { asm volatile("cp.async.wait_group %0;\n" :: "n"(N)); }

__device__ __forceinline__ float tf32_rnaf(float x) {
    unsigned r;
    asm("cvt.rna.tf32.f32 %0, %1;" : "=r"(r) : "f"(x));
    return __uint_as_float(r);
}
__device__ __forceinline__ void mma_tf32(float4& d, const uint4& a,
                                         unsigned b0, unsigned b1) {
    asm volatile(
        "mma.sync.aligned.m16n8k8.row.col.f32.tf32.tf32.f32 "
        "{%0,%1,%2,%3}, {%4,%5,%6,%7}, {%8,%9}, {%0,%1,%2,%3};"
        : "+f"(d.x), "+f"(d.y), "+f"(d.z), "+f"(d.w)
        : "r"(a.x), "r"(a.y), "r"(a.z), "r"(a.w), "r"(b0), "r"(b1));
}
__device__ __forceinline__ float sigmoid_f(float x) {
    return __fdividef(1.0f, 1.0f + __expf(-x));
}
__device__ __forceinline__ float tanh_f(float x) {
    return __fdividef(2.0f, 1.0f + __expf(-2.0f * x)) - 1.0f;
}

// ============================================================================
// Kernel A: xproj = xs @ Wx  (M=32768, N=4096, K=1024), tf32 wmma, cp.async
// (round-3 version, proven; ~1.6ms)
// ============================================================================
__global__ void __launch_bounds__(256) xproj_kernel(const float* __restrict__ xs,
                                                    const float* __restrict__ Wx) {
    constexpr int LDA = 36;
    constexpr int LDB = 132;
    extern __shared__ float smw[];
    float* As = smw;
    float* Bs = smw + 2 * 128 * LDA;

    const int tid = threadIdx.x;
    const int m0 = blockIdx.y * 128;
    const int n0 = blockIdx.x * 128;
    const int w  = tid >> 5;
    const int wm = w & 3;
    const int wn = w >> 2;

    wmma::fragment<wmma::accumulator, 16, 16, 8, float> acc[2][4];
    #pragma unroll
    for (int i = 0; i < 2; i++)
        #pragma unroll
        for (int j = 0; j < 4; j++)
            wmma::fill_fragment(acc[i][j], 0.0f);

    auto load_stage = [&](int st, int k0) {
        #pragma unroll
        for (int it = 0; it < 4; it++) {
            int idx = tid + it * 256;
            int row = idx >> 3;
            int q   = (idx & 7) * 4;
            int m   = m0 + row;
            int bb  = m & (B_ - 1);
            int tt  = m >> 6;
            cp_async16(&As[st * 128 * LDA + row * LDA + q],
                       xs + ((size_t)bb * T_ + tt) * D_ + k0 + q);
        }
        #pragma unroll
        for (int it = 0; it < 4; it++) {
            int idx = tid + it * 256;
            int row = idx >> 5;
            int q   = (idx & 31) * 4;
            cp_async16(&Bs[st * 32 * LDB + row * LDB + q],
                       Wx + (size_t)(k0 + row) * G4_ + n0 + q);
        }
    };

    load_stage(0, 0);
    cp_commit();

    for (int kc = 0; kc < 32; kc++) {
        if (kc + 1 < 32) load_stage((kc + 1) & 1, (kc + 1) * 32);
        cp_commit();
        cp_wait<1>();
        __syncthreads();

        const float* a_base = &As[(kc & 1) * 128 * LDA];
        const float* b_base = &Bs[(kc & 1) * 32 * LDB];
        #pragma unroll
        for (int kk = 0; kk < 32; kk += 8) {
            wmma::fragment<wmma::matrix_a, 16, 16, 8, wmma::precision::tf32, wmma::row_major> af[2];
            wmma::fragment<wmma::matrix_b, 16, 16, 8, wmma::precision::tf32, wmma::row_major> bf[4];
            #pragma unroll
            for (int mi = 0; mi < 2; mi++) {
                wmma::load_matrix_sync(af[mi], a_base + (wm * 32 + mi * 16) * LDA + kk, LDA);
                #pragma unroll
                for (int i = 0; i < af[mi].num_elements; i++)
                    af[mi].x[i] = wmma::__float_to_tf32(af[mi].x[i]);
            }
            #pragma unroll
            for (int nj = 0; nj < 4; nj++) {
                wmma::load_matrix_sync(bf[nj], b_base + kk * LDB + wn * 64 + nj * 16, LDB);
                #pragma unroll
                for (int i = 0; i < bf[nj].num_elements; i++)
                    bf[nj].x[i] = wmma::__float_to_tf32(bf[nj].x[i]);
            }
            #pragma unroll
            for (int mi = 0; mi < 2; mi++)
                #pragma unroll
                for (int nj = 0; nj < 4; nj++)
                    wmma::mma_sync(acc[mi][nj], af[mi], bf[nj], acc[mi][nj]);
        }
        __syncthreads();
    }

    #pragma unroll
    for (int mi = 0; mi < 2; mi++)
        #pragma unroll
        for (int nj = 0; nj < 4; nj++) {
            size_t row = (size_t)(m0 + wm * 32 + mi * 16);
            size_t col = (size_t)(n0 + wn * 64 + nj * 16);
            wmma::store_matrix_sync(g_xproj + row * G4_ + col, acc[mi][nj],
                                    G4_, wmma::mem_row_major);
        }
}

// ============================================================================
// Kernel B: persistent LSTM scan, 128 blocks x 128 threads (4 warps).
//   Block owns h-cols [bIdx*8,+8) x full batch. Warp kq computes the FULL
//   64x32 gate tile over k-quarter kq (256 k = 32 ki): per ki 6 LDS.128 ->
//   16 MMAs, zero fragment redundancy. Cross-warp reduce via DEDICATED sg.
//   2-stage cp.async pipeline. Round-3 atomic split arrive/wait barrier.
// ============================================================================
__global__ void __launch_bounds__(128, 1) lstm_scan_kernel(
    const float* __restrict__ c0, const float* __restrict__ h0,
    const float* __restrict__ Wh, const float* __restrict__ bias,
    float* __restrict__ out)
{
    extern __shared__ float sm[];
    // Whs: [kq(4)][ki2(32)][nh(2)][lane(32)][v(4)] = 32768 floats
    float*  Whs_f = sm;
    float4* Whs   = reinterpret_cast<float4*>(sm);
    // hs: 2 stages x 8192 floats (2048 f4)
    float*  hs_f  = sm + 32768;
    float4* hs    = reinterpret_cast<float4*>(hs_f);
    // sg: DEDICATED reduction staging [kq(4)][row(64) stride 34] = 8704 floats
    float*  sg    = sm + 32768 + 16384;

    const int tid  = threadIdx.x;
    const int lane = tid & 31;
    const int kq   = tid >> 5;          // warp id == k-quarter
    const int bIdx = blockIdx.x;
    const int j0   = bIdx * 8;

    // ---- build Whs (tf32, B-frag permuted):
    //   k = (kq*32+ki2)*8 + (ln&3) + (v&1)*4 ; c = nh*16 + (ln>>2) + (v>>1)*8
    //   gate = c>>3, jj = c&7  ->  Wh[k][gate*H + j0 + jj]
    for (int i = tid; i < 32768; i += 128) {
        int v   = i & 3;
        int ln  = (i >> 2) & 31;
        int nh  = (i >> 7) & 1;
        int ki2 = (i >> 8) & 31;
        int kqq = i >> 13;
        int k = (kqq * 32 + ki2) * 8 + (ln & 3) + ((v & 1) << 2);
        int c = nh * 16 + (ln >> 2) + ((v >> 1) << 3);
        int gate = c >> 3, jc = c & 7;
        Whs_f[i] = tf32_rnaf(__ldg(Wh + (size_t)k * G4_ + gate * H_ + j0 + jc));
    }

    // ---- per-thread ownership: column j = j0 + (tid&7), rows b_q = rbase+16q
    const int rbase = tid >> 3;         // 0..15
    const int jj    = tid & 7;
    const int j     = j0 + jj;
    int bq[4];
    #pragma unroll
    for (int q = 0; q < 4; q++) bq[q] = rbase + q * 16;

    float creg[4], bia[4];
    #pragma unroll
    for (int g = 0; g < 4; g++) bia[g] = __ldg(bias + g * H_ + j);
    #pragma unroll
    for (int q = 0; q < 4; q++) creg[q] = __ldg(c0 + (size_t)bq[q] * H_ + j);

    // ---- h-perm write coords (fixed per thread; strip == q, ki == bIdx)
    const int lane_h = (rbase & 7) * 4 + (jj & 3);
    const int v_h    = ((rbase >> 3) & 1) | ((jj >> 2) << 1);

    // ---- init g_hperm[0] = tf32(h0)
    #pragma unroll
    for (int q = 0; q < 4; q++) {
        size_t f4 = ((size_t)bIdx * 4 + q) * 32 + lane_h;
        g_hperm[0][f4 * 4 + v_h] = tf32_rnaf(__ldg(h0 + (size_t)bq[q] * H_ + j));
    }

    // ---- xproj prefetch
    float xpr[4][4];
    auto prefetch_xp = [&](int t) {
        const float* xp = g_xproj + (size_t)t * B_ * G4_;
        #pragma unroll
        for (int q = 0; q < 4; q++)
            #pragma unroll
            for (int g = 0; g < 4; g++)
                xpr[q][g] = __ldg(xp + (size_t)bq[q] * G4_ + g * H_ + j);
    };
    prefetch_xp(0);

    // ---- initial grid sync (atomic, change-based: replay-safe)
    __syncthreads();
    if (tid == 0) {
        volatile unsigned int* genp = &g_bar_gen;
        unsigned int gen = *genp;
        __threadfence();
        unsigned int old = atomicAdd(&g_bar_count, 1u);
        if (old == 127u) {
            atomicExch(&g_bar_count, 0u);
            __threadfence();
            atomicAdd(&g_bar_gen, 1u);
        } else {
            while (*genp == gen) { }
            __threadfence();
        }
    }
    __syncthreads();

    for (int t = 0; t < T_; t++) {
        const float* hcur  = g_hperm[t & 1];
        float*       hnext = g_hperm[(t + 1) & 1];
        const float4* hc4  = reinterpret_cast<const float4*>(hcur);

        // stage = chunk ch: [kq(4)][dki(4)][strip(4)][lane(32)] f4 (2048 f4)
        auto issue = [&](int ch) {
            float4* dst = hs + (ch & 1) * 2048;
            #pragma unroll
            for (int it = 0; it < 16; it++) {
                int lin   = tid + it * 128;           // < 2048
                int ln    = lin & 31;
                int strip = (lin >> 5) & 3;
                int dki   = (lin >> 7) & 3;
                int kqq   = lin >> 9;
                cp_async16(&dst[lin],
                           &hc4[((size_t)(kqq * 32 + ch * 4 + dki) * 4 + strip) * 32 + ln]);
            }
        };

        issue(0); cp_commit();

        float4 acc[4][4];   // [strip][gate-group]
        #pragma unroll
        for (int s = 0; s < 4; s++)
            #pragma unroll
            for (int g = 0; g < 4; g++)
                acc[s][g] = make_float4(0.f, 0.f, 0.f, 0.f);

        #pragma unroll 1
        for (int ch = 0; ch < 8; ch++) {
            if (ch + 1 < 8) { issue(ch + 1); cp_commit(); }
            if (ch < 7) cp_wait<1>(); else cp_wait<0>();
            __syncthreads();

            const float4* st = hs + (ch & 1) * 2048;
            #pragma unroll
            for (int d = 0; d < 4; d++) {
                int ki2 = ch * 4 + d;
                uint4 a[4];
                #pragma unroll
                for (int s = 0; s < 4; s++)
                    a[s] = *reinterpret_cast<const uint4*>(
                        &st[((kq * 4 + d) * 4 + s) * 32 + lane]);
                uint4 b0 = *reinterpret_cast<const uint4*>(
                    &Whs[((kq * 32 + ki2) * 2 + 0) * 32 + lane]);
                uint4 b1 = *reinterpret_cast<const uint4*>(
                    &Whs[((kq * 32 + ki2) * 2 + 1) * 32 + lane]);
                #pragma unroll
                for (int s = 0; s < 4; s++) {
                    mma_tf32(acc[s][0], a[s], b0.x, b0.y);
                    mma_tf32(acc[s][1], a[s], b0.z, b0.w);
                    mma_tf32(acc[s][2], a[s], b1.x, b1.y);
                    mma_tf32(acc[s][3], a[s], b1.z, b1.w);
                }
            }
            __syncthreads();
        }

        // ---- stage partials: sg[kq][row (stride 34)][col = gate*8 + jj]
        {
            int r  = lane >> 2;
            int c2 = (lane & 3) * 2;
            float* base = sg + (size_t)kq * 64 * 34;
            #pragma unroll
            for (int s = 0; s < 4; s++)
                #pragma unroll
                for (int g = 0; g < 4; g++) {
                    *reinterpret_cast<float2*>(base + (s * 16 + r) * 34 + g * 8 + c2) =
                        make_float2(acc[s][g].x, acc[s][g].y);
                    *reinterpret_cast<float2*>(base + (s * 16 + r + 8) * 34 + g * 8 + c2) =
                        make_float2(acc[s][g].z, acc[s][g].w);
                }
        }
        __syncthreads();

        // ---- reduce 4 k-quarters + fused elementwise (flax order i,f,g,o)
        float hnv[4];
        #pragma unroll
        for (int q = 0; q < 4; q++) {
            float gv[4];
            #pragma unroll
            for (int g = 0; g < 4; g++) {
                float sum = 0.f;
                #pragma unroll
                for (int kk = 0; kk < 4; kk++)
                    sum += sg[((size_t)kk * 64 + bq[q]) * 34 + g * 8 + jj];
                gv[g] = sum;
            }
            float pi = gv[0] + xpr[q][0] + bia[0];
            float pf = gv[1] + xpr[q][1] + bia[1];
            float pg = gv[2] + xpr[q][2] + bia[2];
            float po = gv[3] + xpr[q][3] + bia[3];
            float cn = sigmoid_f(pf) * creg[q] + sigmoid_f(pi) * tanh_f(pg);
            float hn = sigmoid_f(po) * tanh_f(cn);
            creg[q] = cn;
            hnv[q] = hn;
        }

        // ---- write hnext (tf32-rounded, permuted)
        #pragma unroll
        for (int q = 0; q < 4; q++) {
            size_t f4 = ((size_t)bIdx * 4 + q) * 32 + lane_h;
            hnext[f4 * 4 + v_h] = tf32_rnaf(hnv[q]);
        }

        // ---- barrier arrive (round-3 atomic scheme)
        __syncthreads();
        unsigned int mygen = 0;
        if (tid == 0) {
            volatile unsigned int* genp = &g_bar_gen;
            mygen = *genp;
            __threadfence();                    // release h stores
            unsigned int old = atomicAdd(&g_bar_count, 1u);
            if (old == 127u) {
                atomicExch(&g_bar_count, 0u);
                __threadfence();
                atomicAdd(&g_bar_gen, 1u);
            }
        }

        // ---- hidden work between arrive and wait: ys stores + next prefetch
        #pragma unroll
        for (int q = 0; q < 4; q++)
            out[2 * B_ * H_ + ((size_t)bq[q] * T_ + t) * H_ + j] = hnv[q];
        if (t == T_ - 1) {
            #pragma unroll
            for (int q = 0; q < 4; q++)
                out[B_ * H_ + (size_t)bq[q] * H_ + j] = hnv[q];
        }
        if (t + 1 < T_) prefetch_xp(t + 1);

        // ---- barrier wait
        if (tid == 0) {
            volatile unsigned int* genp = &g_bar_gen;
            while (*genp == mygen) { }
            __threadfence();                    // acquire
        }
        __syncthreads();
    }

    // cT
    #pragma unroll
    for (int q = 0; q < 4; q++)
        out[(size_t)bq[q] * H_ + j] = creg[q];
}

// ============================================================================
// Launch. Inputs: c0, h0, xs, Wx, Wh, b. Output fp32: [cT][hT][ys]
// ============================================================================
extern "C" void kernel_launch(void* const* d_in, const int* in_sizes, int n_in,
                              void* d_out, int out_size) {
    const float* c0   = (const float*)d_in[0];
    const float* h0   = (const float*)d_in[1];
    const float* xs   = (const float*)d_in[2];
    const float* Wx   = (const float*)d_in[3];
    const float* Wh   = (const float*)d_in[4];
    const float* bias = (const float*)d_in[5];
    float* out = (float*)d_out;

    constexpr int XPROJ_SMEM = (2 * 128 * 36 + 2 * 32 * 132) * 4;     // 70,656 B
    constexpr int SCAN_SMEM  = (32768 + 2 * 8192 + 8704) * 4;         // 231,424 B
    cudaFuncSetAttribute(xproj_kernel,
                         cudaFuncAttributeMaxDynamicSharedMemorySize, XPROJ_SMEM);
    cudaFuncSetAttribute(lstm_scan_kernel,
                         cudaFuncAttributeMaxDynamicSharedMemorySize, SCAN_SMEM);

    dim3 gridA(G4_ / 128, (T_ * B_) / 128);   // 32 x 256 blocks
    xproj_kernel<<<gridA, 256, XPROJ_SMEM>>>(xs, Wx);
    lstm_scan_kernel<<<128, 128, SCAN_SMEM>>>(c0, h0, Wh, bias, out);
}